// round 5
// baseline (speedup 1.0000x reference)
#include <cuda_runtime.h>

#define B_   64
#define T_   512
#define D_   256
#define U_   512
#define G3   1536
#define NBLK 128
#define NTHR 512
#define SCAN_SMEM (131072)   // 128KB dynamic

// ---------------- device scratch (no allocations allowed) ----------------
__device__ float g_gx[(size_t)2 * T_ * B_ * G3];   // [dir][t][b][3U] gate preacts
__device__ float g_h [2 * B_ * U_];                // hidden state per dir
__device__ float g_u [2 * B_ * U_];                // update gate per step
__device__ float g_rh[2 * B_ * U_];                // r * h per step
__device__ unsigned int          g_barc[2] = {0, 0};
__device__ volatile unsigned int g_barg[2] = {0, 0};

// Per-direction software barrier over 64 blocks. Replay-safe.
__device__ __forceinline__ void dir_barrier(int dir) {
    __threadfence();
    __syncthreads();
    if (threadIdx.x == 0) {
        unsigned g = g_barg[dir];
        unsigned prev = atomicAdd(&g_barc[dir], 1u);
        if (prev == 63u) {
            g_barc[dir] = 0u;
            __threadfence();
            g_barg[dir] = g + 1u;
        } else {
            while (g_barg[dir] == g) { __nanosleep(32); }
        }
    }
    __syncthreads();
}

__device__ __forceinline__ float sigmoidf_(float z) {
    return 1.0f / (1.0f + __expf(-z));
}

// ---------------- packed f32x2 helpers (PTX-only; ptxas won't auto-fuse) ---
__device__ __forceinline__ void ffma2(unsigned long long& d,
                                      unsigned long long a,
                                      unsigned long long b) {
    asm("fma.rn.f32x2 %0, %1, %2, %0;" : "+l"(d) : "l"(a), "l"(b));
}
__device__ __forceinline__ unsigned long long dup2(float x) {
    unsigned long long r; unsigned u = __float_as_uint(x);
    asm("mov.b64 %0, {%1, %1};" : "=l"(r) : "r"(u));
    return r;
}
__device__ __forceinline__ float2 up2(unsigned long long v) {
    float2 f;
    asm("mov.b64 {%0, %1}, %2;" : "=f"(f.x), "=f"(f.y) : "l"(v));
    return f;
}

// =====================================================================
// Kernel A: input projections for BOTH directions in one GEMM (FFMA2).
// =====================================================================
__global__ void __launch_bounds__(256) k_inproj(
    const float* __restrict__ x,
    const float* __restrict__ Wxf,
    const float* __restrict__ Wxb)
{
    __shared__ __align__(16) float As[16 * 64];   // [k][m]
    __shared__ __align__(16) float Bs[16 * 64];   // [k][n]

    const int tid = threadIdx.x;
    const int m0  = blockIdx.x * 64;
    const int n0g = blockIdx.y * 64;
    const int dir = (n0g >= G3) ? 1 : 0;
    const float* __restrict__ W = dir ? Wxb : Wxf;
    const int n0 = n0g - dir * G3;

    const int bg = tid >> 4;
    const int ng = tid & 15;
    const int ar = tid >> 2, aq = tid & 3;
    const int bk = tid >> 4, bc = tid & 15;

    unsigned long long acc[2][4];
#pragma unroll
    for (int p = 0; p < 2; p++)
#pragma unroll
        for (int j = 0; j < 4; j++) acc[p][j] = 0ull;

    for (int k0 = 0; k0 < D_; k0 += 16) {
        float4 av = *reinterpret_cast<const float4*>(x + (size_t)(m0 + ar) * D_ + k0 + aq * 4);
        float4 bv = *reinterpret_cast<const float4*>(W + (size_t)(k0 + bk) * G3 + n0 + bc * 4);
        __syncthreads();
        As[(aq * 4 + 0) * 64 + ar] = av.x;
        As[(aq * 4 + 1) * 64 + ar] = av.y;
        As[(aq * 4 + 2) * 64 + ar] = av.z;
        As[(aq * 4 + 3) * 64 + ar] = av.w;
        *reinterpret_cast<float4*>(&Bs[bk * 64 + bc * 4]) = bv;
        __syncthreads();
#pragma unroll
        for (int kk = 0; kk < 16; kk++) {
            ulonglong2 a2 = *reinterpret_cast<const ulonglong2*>(&As[kk * 64 + bg * 4]);
            float4 b4 = *reinterpret_cast<const float4*>(&Bs[kk * 64 + ng * 4]);
            unsigned long long w0 = dup2(b4.x), w1 = dup2(b4.y),
                               w2 = dup2(b4.z), w3 = dup2(b4.w);
            ffma2(acc[0][0], a2.x, w0); ffma2(acc[0][1], a2.x, w1);
            ffma2(acc[0][2], a2.x, w2); ffma2(acc[0][3], a2.x, w3);
            ffma2(acc[1][0], a2.y, w0); ffma2(acc[1][1], a2.y, w1);
            ffma2(acc[1][2], a2.y, w2); ffma2(acc[1][3], a2.y, w3);
        }
    }

    float accf[4][4];
#pragma unroll
    for (int p = 0; p < 2; p++)
#pragma unroll
        for (int j = 0; j < 4; j++) {
            float2 f = up2(acc[p][j]);
            accf[2 * p][j]     = f.x;
            accf[2 * p + 1][j] = f.y;
        }

#pragma unroll
    for (int i = 0; i < 4; i++) {
        int m = m0 + bg * 4 + i;
        int b = m >> 9;
        int s = m & 511;
        int t = dir ? (T_ - 1 - s) : s;
        float* dst = g_gx + (((size_t)dir * T_ + t) * B_ + b) * G3 + n0 + ng * 4;
        *reinterpret_cast<float4*>(dst) =
            make_float4(accf[i][0], accf[i][1], accf[i][2], accf[i][3]);
    }
}

// =====================================================================
// Kernel B: persistent bidirectional GRU scan. 512 thr, 128KB dyn smem.
// Per phase: single-shot stage of h (or r*h) into smem (high-MLP ldcg),
// one sync, straight FFMA2 GEMM over the kg's K-range, K-split reduce.
// Phase A: 16 kg x K=32, micro 8b x 4c (tile 64b x 16c per block).
// Phase B: 32 kg x K=16, micro 8b x 4c (tile 64b x  8c per block).
// =====================================================================
extern __shared__ float s_u[];

__global__ void __launch_bounds__(NTHR, 1) k_scan(
    const float* __restrict__ Whf, const float* __restrict__ Whb,
    const float* __restrict__ bf,  const float* __restrict__ bb,
    float* __restrict__ out)
{
    const int tid = threadIdx.x;
    const int blk = blockIdx.x;
    const int dir = blk >> 6;
    const int sub = blk & 63;

    const float* __restrict__ Wh   = dir ? Whb : Whf;
    const float* __restrict__ bias = dir ? bb : bf;
    float* hbuf  = g_h  + dir * (B_ * U_);
    float* ubuf  = g_u  + dir * (B_ * U_);
    float* rhbuf = g_rh + dir * (B_ * U_);
    const float* gxbase = g_gx + (size_t)dir * T_ * B_ * G3;

    const int cbaseA = sub * 16;   // cols within [0,1024)
    const int cbaseB = sub * 8;    // cols within [0,512)

    // zero h (65536 floats, exactly 1 per thread)
    __stcg(&g_h[blk * NTHR + tid], 0.0f);
    dir_barrier(dir);

    // ---- Phase A mapping: 16 kg x 32 threads; micro 8b x 4c
    const int kgA = tid >> 5;                  // 0..15, K range 32
    const int tA  = tid & 31;
    const int b0A = (tA >> 2) << 3;            // 0,8,..,56
    const int c0A = (tA & 3) << 2;             // 0,4,8,12
    const int kbA = kgA << 5;
    const int qA  = tA & 1;                    // staging kquad base
    const int blA = tA >> 1;                   // staging b base
    const int sA_base = kgA << 11;             // *2048 floats
    // outputs (2 per thread)
    const int oidA = tid << 1;
    const int bA0 = oidA >> 4,       cgA0 = cbaseA + (oidA & 15);
    const int bA1 = (oidA + 1) >> 4, cgA1 = cbaseA + ((oidA + 1) & 15);
    const float biasA0 = __ldg(bias + cgA0);
    const float biasA1 = __ldg(bias + cgA1);

    // ---- Phase B mapping: 32 kg x 16 threads; micro 8b x 4c
    const int kgB = tid >> 4;                  // 0..31, K range 16
    const int tB  = tid & 15;
    const int b0B = (tB >> 1) << 3;            // 0,8,..,56
    const int c0B = (tB & 1) << 2;             // 0,4
    const int kbB = kgB << 4;
    const int sB_base = kgB << 10;             // *1024 floats
    const int bB  = tid >> 3;
    const int cgB = cbaseB + (tid & 7);
    const float biasB = __ldg(bias + 1024 + cgB);

    for (int t = 0; t < T_; t++) {
        const float* gxt = gxbase + (size_t)t * B_ * G3;

        // ================= Phase A: z = h @ Wh[:, :1024] =================
        {
            float gxa0 = __ldg(gxt + (size_t)bA0 * G3 + cgA0);
            float gxa1 = __ldg(gxt + (size_t)bA1 * G3 + cgA1);

            // single-shot stage: this kg's h slice [32k x 64b] transposed
#pragma unroll
            for (int w = 0; w < 2; w++) {
                float4 v[8];
#pragma unroll
                for (int j = 0; j < 8; j++) {
                    int jj = w * 8 + j;
                    int kq = qA + ((jj >> 2) << 1);
                    int b  = blA + ((jj & 3) << 4);
                    v[j] = __ldcg(reinterpret_cast<const float4*>(
                        hbuf + (size_t)b * U_ + kbA + (kq << 2)));
                }
#pragma unroll
                for (int j = 0; j < 8; j++) {
                    int jj = w * 8 + j;
                    int kq = qA + ((jj >> 2) << 1);
                    int b  = blA + ((jj & 3) << 4);
                    int base = sA_base + (kq << 2) * 64 + b;
                    s_u[base]       = v[j].x;
                    s_u[base + 64]  = v[j].y;
                    s_u[base + 128] = v[j].z;
                    s_u[base + 192] = v[j].w;
                }
            }
            __syncthreads();

            unsigned long long acc[4][4];
#pragma unroll
            for (int p = 0; p < 4; p++)
#pragma unroll
                for (int j = 0; j < 4; j++) acc[p][j] = 0ull;

            const float* wp = Wh + (size_t)kbA * G3 + cbaseA + c0A;
            const float* sp = s_u + sA_base + b0A;
#pragma unroll 8
            for (int kk = 0; kk < 32; kk++) {
                ulonglong2 a01 = *reinterpret_cast<const ulonglong2*>(sp + kk * 64);
                ulonglong2 a23 = *reinterpret_cast<const ulonglong2*>(sp + kk * 64 + 4);
                float4 w4 = __ldg(reinterpret_cast<const float4*>(wp + (size_t)kk * G3));
                unsigned long long w0 = dup2(w4.x), w1 = dup2(w4.y),
                                   w2 = dup2(w4.z), w3 = dup2(w4.w);
                ffma2(acc[0][0], a01.x, w0); ffma2(acc[0][1], a01.x, w1);
                ffma2(acc[0][2], a01.x, w2); ffma2(acc[0][3], a01.x, w3);
                ffma2(acc[1][0], a01.y, w0); ffma2(acc[1][1], a01.y, w1);
                ffma2(acc[1][2], a01.y, w2); ffma2(acc[1][3], a01.y, w3);
                ffma2(acc[2][0], a23.x, w0); ffma2(acc[2][1], a23.x, w1);
                ffma2(acc[2][2], a23.x, w2); ffma2(acc[2][3], a23.x, w3);
                ffma2(acc[3][0], a23.y, w0); ffma2(acc[3][1], a23.y, w1);
                ffma2(acc[3][2], a23.y, w2); ffma2(acc[3][3], a23.y, w3);
            }
            __syncthreads();
#pragma unroll
            for (int p = 0; p < 4; p++)
#pragma unroll
                for (int j = 0; j < 4; j++) {
                    float2 f = up2(acc[p][j]);
                    s_u[(kgA << 10) + (b0A + 2 * p)     * 16 + c0A + j] = f.x;
                    s_u[(kgA << 10) + (b0A + 2 * p + 1) * 16 + c0A + j] = f.y;
                }
            __syncthreads();

            float z0 = 0.0f, z1 = 0.0f;
#pragma unroll
            for (int kg = 0; kg < 16; kg++) {
                float2 v = *reinterpret_cast<const float2*>(&s_u[(kg << 10) + oidA]);
                z0 += v.x; z1 += v.y;
            }
            float sg0 = sigmoidf_(z0 + gxa0 + biasA0);
            float sg1 = sigmoidf_(z1 + gxa1 + biasA1);
            if (cgA0 < U_) {
                __stcg(ubuf + bA0 * U_ + cgA0, sg0);
            } else {
                float hold = __ldcg(hbuf + bA0 * U_ + cgA0 - U_);
                __stcg(rhbuf + bA0 * U_ + cgA0 - U_, sg0 * hold);
            }
            if (cgA1 < U_) {
                __stcg(ubuf + bA1 * U_ + cgA1, sg1);
            } else {
                float hold = __ldcg(hbuf + bA1 * U_ + cgA1 - U_);
                __stcg(rhbuf + bA1 * U_ + cgA1 - U_, sg1 * hold);
            }
        }
        dir_barrier(dir);

        // ================= Phase B: c = (r*h) @ Wh[:, 1024:] =============
        {
            float gxb = __ldg(gxt + (size_t)bB * G3 + 1024 + cgB);

#pragma unroll
            for (int w = 0; w < 2; w++) {
                float4 v[8];
#pragma unroll
                for (int j = 0; j < 8; j++) {
                    int jj = w * 8 + j;
                    int kq = jj >> 2;                 // 0..3
                    int b  = tB + ((jj & 3) << 4);
                    v[j] = __ldcg(reinterpret_cast<const float4*>(
                        rhbuf + (size_t)b * U_ + kbB + (kq << 2)));
                }
#pragma unroll
                for (int j = 0; j < 8; j++) {
                    int jj = w * 8 + j;
                    int kq = jj >> 2;
                    int b  = tB + ((jj & 3) << 4);
                    int base = sB_base + (kq << 2) * 64 + b;
                    s_u[base]       = v[j].x;
                    s_u[base + 64]  = v[j].y;
                    s_u[base + 128] = v[j].z;
                    s_u[base + 192] = v[j].w;
                }
            }
            __syncthreads();

            unsigned long long acc[4][4];
#pragma unroll
            for (int p = 0; p < 4; p++)
#pragma unroll
                for (int j = 0; j < 4; j++) acc[p][j] = 0ull;

            const float* wp = Wh + (size_t)kbB * G3 + 1024 + cbaseB + c0B;
            const float* sp = s_u + sB_base + b0B;
#pragma unroll
            for (int kk = 0; kk < 16; kk++) {
                ulonglong2 a01 = *reinterpret_cast<const ulonglong2*>(sp + kk * 64);
                ulonglong2 a23 = *reinterpret_cast<const ulonglong2*>(sp + kk * 64 + 4);
                float4 w4 = __ldg(reinterpret_cast<const float4*>(wp + (size_t)kk * G3));
                unsigned long long w0 = dup2(w4.x), w1 = dup2(w4.y),
                                   w2 = dup2(w4.z), w3 = dup2(w4.w);
                ffma2(acc[0][0], a01.x, w0); ffma2(acc[0][1], a01.x, w1);
                ffma2(acc[0][2], a01.x, w2); ffma2(acc[0][3], a01.x, w3);
                ffma2(acc[1][0], a01.y, w0); ffma2(acc[1][1], a01.y, w1);
                ffma2(acc[1][2], a01.y, w2); ffma2(acc[1][3], a01.y, w3);
                ffma2(acc[2][0], a23.x, w0); ffma2(acc[2][1], a23.x, w1);
                ffma2(acc[2][2], a23.x, w2); ffma2(acc[2][3], a23.x, w3);
                ffma2(acc[3][0], a23.y, w0); ffma2(acc[3][1], a23.y, w1);
                ffma2(acc[3][2], a23.y, w2); ffma2(acc[3][3], a23.y, w3);
            }
            __syncthreads();
#pragma unroll
            for (int p = 0; p < 4; p++)
#pragma unroll
                for (int j = 0; j < 4; j++) {
                    float2 f = up2(acc[p][j]);
                    s_u[(kgB << 9) + (b0B + 2 * p)     * 8 + c0B + j] = f.x;
                    s_u[(kgB << 9) + (b0B + 2 * p + 1) * 8 + c0B + j] = f.y;
                }
            __syncthreads();

            float z = 0.0f;
#pragma unroll
            for (int kg = 0; kg < 32; kg++) z += s_u[(kg << 9) + tid];
            float hh   = tanhf(z + gxb + biasB);
            float uu   = __ldcg(ubuf + bB * U_ + cgB);
            float hold = __ldcg(hbuf + bB * U_ + cgB);
            float hnew = hold + uu * (hh - hold);
            __stcg(hbuf + bB * U_ + cgB, hnew);
            out[((size_t)bB * T_ + t) * 1024 + dir * U_ + cgB] = hnew;
        }
        dir_barrier(dir);
    }
}

// =====================================================================
extern "C" void kernel_launch(void* const* d_in, const int* in_sizes, int n_in,
                              void* d_out, int out_size)
{
    const float* x   = (const float*)d_in[0];
    const float* Wxf = (const float*)d_in[1];
    const float* Whf = (const float*)d_in[2];
    const float* bf  = (const float*)d_in[3];
    const float* Wxb = (const float*)d_in[4];
    const float* Whb = (const float*)d_in[5];
    const float* bb  = (const float*)d_in[6];
    float* out = (float*)d_out;

    // non-stream API; idempotent; safe under graph capture
    cudaFuncSetAttribute(k_scan, cudaFuncAttributeMaxDynamicSharedMemorySize, SCAN_SMEM);

    dim3 gA(512, 48);
    k_inproj<<<gA, 256>>>(x, Wxf, Wxb);
    k_scan<<<NBLK, NTHR, SCAN_SMEM>>>(Whf, Whb, bf, bb, out);
}